// round 15
// baseline (speedup 1.0000x reference)
#include <cuda_runtime.h>

#define NN 2000
#define PS 516               // step1 f32 plane stride (floats)
#define ARRF 4128
#define BPL 264              // step2 bf16x2 plane stride (u32 words; 264%32==8)

__device__ int g_nbrs[NN * 16];
__device__ __align__(16) unsigned short g_F1b[(size_t)NN * 4096];  // bf16 F1, 16 MB
__device__ double g_gsum[48];

// ---------------- shared layouts ---------------------------------------------
struct __align__(16) Sm2 {
    unsigned Asp[48 * BPL];  // bf16x2 contraction arrays [arr*8+c2][swz(pos)]
    float P[16896];          // s0 staging (4 x 4224 f32) then GEMM partials (16384 f32)
    float4 Wp[768];          // [kp][h] = {We0,We1,Wo0,Wo1}
    float Wvt[1536];         // [cci][h] transposed v-block weights
    float v0[256], v1s[256], v2s[256];
    float v1p[4][256], v2p[4][256];
    float rowt[256], colt[256];
    float red[512];
    float bb[16];
    int nbrs_i[16];
    int nbrs_j[16][16];
    __align__(16) int pi[16][16];
};

struct __align__(16) Sm1 {
    float Asp[ARRF];         // dense array (= s1 = s2 = d2), swizzled f32
    float4 Wp[128];          // combined dense weights [kp][h]
    float Wvt[1536];
    float wd1[256], wd2[256];
    float v0[256], v1s[256];
    float rowt[256], colt[256], corr[256];
    float red[8][8];
    float bb[16];
    int nbrs_i[16];
    int nbrs_j[16][16];
    __align__(16) int pi[16][16];
};

__device__ __forceinline__ unsigned sptr(const void* p) {
    return (unsigned)__cvta_generic_to_shared(p);
}
__device__ __forceinline__ float sum2(unsigned long long u) {
    return __uint_as_float((unsigned)u) + __uint_as_float((unsigned)(u >> 32));
}
__device__ __forceinline__ float lo2(unsigned long long u) {
    return __uint_as_float((unsigned)u);
}
__device__ __forceinline__ float hi2(unsigned long long u) {
    return __uint_as_float((unsigned)(u >> 32));
}
__device__ __forceinline__ unsigned cvtb2(float lo, float hi) {
    unsigned r;
    asm("cvt.rn.bf16x2.f32 %0, %1, %2;" : "=r"(r) : "f"(hi), "f"(lo));
    return r;
}
// bf16x2 (u32) -> packed f32x2 (u64): lo half <<16, hi half masked
__device__ __forceinline__ unsigned long long b2f2(unsigned v) {
    unsigned lo = v << 16;
    unsigned hi = v & 0xffff0000u;
    return (unsigned long long)lo | ((unsigned long long)hi << 32);
}
#define FMA2(acc, x, y) \
    asm("fma.rn.f32x2 %0, %1, %2, %3;" : "=l"(acc) : "l"(x), "l"(y), "l"(acc))
#define ADD2(acc, x) \
    asm("add.rn.f32x2 %0, %0, %1;" : "+l"(acc) : "l"(x))
#define LDW2(we, wo, a) \
    asm("ld.shared.v2.b64 {%0,%1}, [%2];" : "=l"(we), "=l"(wo) : "r"(a))
__device__ __forceinline__ int swzf(int x, int y) {
    return x * 16 + (((y ^ x) + 5 * x) & 15);
}
__device__ __forceinline__ void unrank(int u, int& x1, int& y1, int& x2,
                                       int& y2, bool& diag) {
    if (u < 120) {
        int a = 0, rem = u;
        while (rem >= 15 - a) { rem -= 15 - a; ++a; }
        x1 = a; y1 = a + 1 + rem; x2 = y1; y2 = x1; diag = false;
    } else {
        int d = u - 120;
        x1 = 2 * d; y1 = 2 * d; x2 = 2 * d + 1; y2 = 2 * d + 1; diag = true;
    }
}

// ---------------- kernel 1: neighbor extraction + zero g --------------------
__global__ void nbrs_kernel(const float* __restrict__ adj) {
    if (blockIdx.x == 0 && threadIdx.x < 48) g_gsum[threadIdx.x] = 0.0;
    int w = blockIdx.x * (blockDim.x >> 5) + (threadIdx.x >> 5);
    int lane = threadIdx.x & 31;
    if (w >= NN) return;
    const float* row = adj + (size_t)w * NN;
    int cnt = 0;
    for (int base = 0; base < NN; base += 32) {
        int col = base + lane;
        float v = (col < NN) ? row[col] : 0.f;
        unsigned mask = __ballot_sync(0xffffffffu, v > 0.5f);
        if (v > 0.5f) {
            int pos = cnt + __popc(mask & ((1u << lane) - 1u));
            if (pos < 16) g_nbrs[w * 16 + pos] = col;
        }
        cnt += __popc(mask);
    }
}

// ---------------- kernel 2: F0 channel sums ---------------------------------
__global__ void f0sum_kernel(const float* __restrict__ X) {
    int idx = blockIdx.x * 256 + threadIdx.x;
    float loc[16];
#pragma unroll
    for (int c = 0; c < 16; ++c) loc[c] = 0.f;
    if (idx < NN * 16) {
        int node = g_nbrs[idx];
#pragma unroll
        for (int c = 0; c < 16; ++c) loc[c] = X[node * 16 + c];
    }
#pragma unroll
    for (int c = 0; c < 16; ++c) {
        float v = loc[c];
#pragma unroll
        for (int o = 16; o; o >>= 1) v += __shfl_xor_sync(0xffffffffu, v, o);
        loc[c] = v;
    }
    __shared__ float sh[8][16];
    int wid = threadIdx.x >> 5, lane = threadIdx.x & 31;
    if (lane == 0) {
#pragma unroll
        for (int c = 0; c < 16; ++c) sh[wid][c] = loc[c];
    }
    __syncthreads();
    if (threadIdx.x < 16) {
        float s = 0.f;
#pragma unroll
        for (int w = 0; w < 8; ++w) s += sh[w][threadIdx.x];
        atomicAdd(&g_gsum[threadIdx.x], (double)s);
    }
}

// ---------------- kernel 3: layer-1 step (diagonal F0 specialization) -------
__global__ __launch_bounds__(256, 4) void step1_kernel(
    const float* __restrict__ X, const float* __restrict__ Wg,
    const float* __restrict__ bg) {
    __shared__ Sm1 sm;
    const int i = blockIdx.x;
    const int tid = threadIdx.x;

    if (tid < 16) {
        sm.nbrs_i[tid] = g_nbrs[i * 16 + tid];
        sm.bb[tid] = bg[tid];
    }
    if (tid < 128) {  // combined dense weights: even {2,4,10}, odd {3,5,11}
        int kp = tid >> 4, h = tid & 15, cc = kp * 2;
        const float* wb = Wg + h * 288;
        sm.Wp[tid] = make_float4(
            wb[32 + cc] + wb[64 + cc] + wb[160 + cc],
            wb[33 + cc] + wb[65 + cc] + wb[161 + cc],
            wb[48 + cc] + wb[80 + cc] + wb[176 + cc],
            wb[49 + cc] + wb[81 + cc] + wb[177 + cc]);
    }
    {  // diag-correction weights (all 256 threads)
        int h = tid >> 4, c = tid & 15;
        const float* wb = Wg + h * 288;
        sm.wd1[tid] = wb[c] + wb[16 + c];
        sm.wd2[tid] = wb[96 + c] + wb[112 + c] + wb[128 + c] + wb[144 + c];
    }
#pragma unroll
    for (int idx = tid; idx < 1536; idx += 256) {
        int cci = idx >> 4, h = idx & 15;
        sm.Wvt[idx] = Wg[h * 288 + 192 + cci];
    }
    __syncthreads();
    {
        int m = tid >> 4, aa = tid & 15;
        sm.nbrs_j[m][aa] = g_nbrs[sm.nbrs_i[m] * 16 + aa];
    }
    __syncthreads();
    {
        int m = tid >> 4, aa = tid & 15;
        int tgt = sm.nbrs_i[aa];
        int p = -1;
#pragma unroll
        for (int q = 0; q < 16; ++q)
            if (sm.nbrs_j[m][q] == tgt) p = q;
        sm.pi[m][aa] = p;
    }
    __syncthreads();

    // phase A: dense[m][a][c] = xv; v1 = col sums (per-thread accumulator)
    {
        const int xa = tid >> 4, c = tid & 15;
        float v1acc = 0.f;
        float* asw = sm.Asp + (c >> 1) * PS + (c & 1);
#pragma unroll
        for (int m = 0; m < 16; ++m) {
            int pa = sm.pi[m][xa];
            float xv = 0.f;
            if (pa >= 0) xv = X[sm.nbrs_j[m][pa] * 16 + c];
            v1acc += xv;
            asw[swzf(m, xa) * 2] = xv;
        }
        sm.v1s[xa * 16 + c] = v1acc;
    }
    __syncthreads();
    {  // v0[m][c] = row sums
        int m = tid >> 4, cx = tid & 15;
        const float* s2b = sm.Asp + (cx >> 1) * PS + (cx & 1);
        float s = 0.f;
#pragma unroll
        for (int a2 = 0; a2 < 16; ++a2) s += s2b[swzf(m, a2) * 2];
        sm.v0[m * 16 + cx] = s;
    }
    __syncthreads();
    {  // rowt / colt / corr, thread = (x, h)
        int x = tid >> 4, h = tid & 15;
        float r = 0.f, ct = 0.f, co = 0.f;
#pragma unroll
        for (int cc = 0; cc < 16; ++cc) {
            float a0 = sm.v0[x * 16 + cc];
            float a1 = sm.v1s[x * 16 + cc];
            r += a0 * sm.Wvt[cc * 16 + h] +
                 a1 * (sm.Wvt[(32 + cc) * 16 + h] + sm.Wvt[(64 + cc) * 16 + h]);
            ct += a0 * sm.Wvt[(16 + cc) * 16 + h] +
                  a1 * (sm.Wvt[(48 + cc) * 16 + h] + sm.Wvt[(80 + cc) * 16 + h]);
            float dd = sm.Asp[(cc >> 1) * PS + swzf(x, x) * 2 + (cc & 1)];
            co += a1 * sm.wd1[h * 16 + cc] + dd * sm.wd2[h * 16 + cc];
        }
        sm.rowt[x * 16 + h] = r;
        sm.colt[x * 16 + h] = ct;
        sm.corr[x * 16 + h] = co;
    }
    __syncthreads();

    // dense GEMM: 2 h-halves x 128 transpose-pair units
    const int hs = tid >> 7, u = tid & 127;
    int x1, y1, x2, y2;
    bool diag;
    unrank(u, x1, y1, x2, y2, diag);
    const int sw1 = swzf(x1, y1), sw2 = swzf(x2, y2);
    unsigned long long acc1[8], acc2[8];
#pragma unroll
    for (int h = 0; h < 8; ++h) { acc1[h] = 0ull; acc2[h] = 0ull; }
    unsigned wadr = sptr(sm.Wp) + hs * 128;
#pragma unroll
    for (int kp = 0; kp < 8; ++kp) {
        const float* pl = sm.Asp + kp * PS;
        unsigned long long va = *(const unsigned long long*)(pl + sw1 * 2);
        unsigned long long vb = *(const unsigned long long*)(pl + sw2 * 2);
        unsigned long long t1 = diag ? va : vb;
        unsigned long long t2 = diag ? vb : va;
#pragma unroll
        for (int hh = 0; hh < 8; ++hh) {
            unsigned long long we, wo;
            LDW2(we, wo, wadr + kp * 256 + hh * 16);
            FMA2(acc1[hh], va, we);
            FMA2(acc1[hh], t1, wo);
            FMA2(acc2[hh], vb, we);
            FMA2(acc2[hh], t2, wo);
        }
    }
    // finalize: bias + row/col terms (+ diag corr), ReLU, write F1 (bf16), g-accum
    float g8[8];
    {
        float v1v[8], v2v[8];
#pragma unroll
        for (int hh = 0; hh < 8; ++hh) {
            int h = hs * 8 + hh;
            float v = sum2(acc1[hh]) + sm.rowt[x1 * 16 + h] +
                      sm.colt[y1 * 16 + h] + sm.bb[h];
            if (diag) v += sm.corr[x1 * 16 + h];
            v1v[hh] = fmaxf(v, 0.f);
            float w2 = sum2(acc2[hh]) + sm.rowt[x2 * 16 + h] +
                       sm.colt[y2 * 16 + h] + sm.bb[h];
            if (diag) w2 += sm.corr[x2 * 16 + h];
            v2v[hh] = fmaxf(w2, 0.f);
            g8[hh] = v1v[hh] + v2v[hh];
        }
        uint4 o1 = make_uint4(cvtb2(v1v[0], v1v[1]), cvtb2(v1v[2], v1v[3]),
                              cvtb2(v1v[4], v1v[5]), cvtb2(v1v[6], v1v[7]));
        *(uint4*)(g_F1b + (size_t)i * 4096 + (x1 * 16 + y1) * 16 + hs * 8) = o1;
        uint4 o2 = make_uint4(cvtb2(v2v[0], v2v[1]), cvtb2(v2v[2], v2v[3]),
                              cvtb2(v2v[4], v2v[5]), cvtb2(v2v[6], v2v[7]));
        *(uint4*)(g_F1b + (size_t)i * 4096 + (x2 * 16 + y2) * 16 + hs * 8) = o2;
    }
#pragma unroll
    for (int hh = 0; hh < 8; ++hh) {
#pragma unroll
        for (int o = 16; o; o >>= 1)
            g8[hh] += __shfl_xor_sync(0xffffffffu, g8[hh], o);
    }
    const int wid = tid >> 5, lane = tid & 31;
    if (lane == 0) {
#pragma unroll
        for (int hh = 0; hh < 8; ++hh) sm.red[wid][hh] = g8[hh];
    }
    __syncthreads();
    if (tid < 16) {
        int hs2 = tid >> 3, hh = tid & 7;
        float s = sm.red[hs2 * 4 + 0][hh] + sm.red[hs2 * 4 + 1][hh] +
                  sm.red[hs2 * 4 + 2][hh] + sm.red[hs2 * 4 + 3][hh];
        atomicAdd(&g_gsum[16 + hs2 * 8 + hh], (double)s);
    }
}

// ---------------- kernel 4: layer-2 step (bf16 gathers + bf16 Asp) ----------
__global__ __launch_bounds__(1024, 1) void step2_kernel(
    const float* __restrict__ Wg, const float* __restrict__ bg) {
    extern __shared__ char smraw[];
    Sm2* sm = reinterpret_cast<Sm2*>(smraw);
    const int i = blockIdx.x;
    const int tid = threadIdx.x;
    const int g = tid >> 8, t = tid & 255;
    const int a = t >> 4, c2 = (t & 15) >> 1, hb = t & 1;

    if (tid < 16) sm->nbrs_i[tid] = g_nbrs[i * 16 + tid];
    if (tid < 768) {
        int kp = tid >> 4, h = tid & 15, arr = kp >> 3, cc = (kp & 7) * 2;
        const float* wb = Wg + h * 288 + arr * 32 + cc;
        sm->Wp[tid] = make_float4(wb[0], wb[1], wb[16], wb[17]);
    }
    for (int idx = tid; idx < 1536; idx += 1024) {
        int cci = idx >> 4, h = idx & 15;
        sm->Wvt[idx] = Wg[h * 288 + 192 + cci];
    }
    if (tid >= 768 && tid < 784) sm->bb[tid - 768] = bg[tid - 768];
    __syncthreads();
    if (tid < 256) {
        int m = tid >> 4, aa = tid & 15;
        sm->nbrs_j[m][aa] = g_nbrs[sm->nbrs_i[m] * 16 + aa];
    }
    __syncthreads();
    if (tid < 256) {
        int m = tid >> 4, aa = tid & 15;
        int tgt = sm->nbrs_i[aa];
        int p = -1;
#pragma unroll
        for (int q = 0; q < 16; ++q)
            if (sm->nbrs_j[m][q] == tgt) p = q;
        sm->pi[m][aa] = p;
    }
    __syncthreads();

    // ---------------- Phase A: bf16 gathers straight from L1/L2 -------------
    unsigned long long s0a[8];
#pragma unroll
    for (int k = 0; k < 8; ++k) s0a[k] = 0ull;
    float v1l = 0.f, v1r = 0.f, v2l = 0.f, v2r = 0.f;
    unsigned* Au = sm->Asp;

#pragma unroll
    for (int iter = 0; iter < 4; ++iter) {
        const int m = iter * 4 + g;
        const int j = sm->nbrs_i[m];
        const unsigned* Fj = (const unsigned*)g_F1b + (size_t)j * 2048;
        const int pa = sm->pi[m][a];
        const int pm = sm->pi[m][m];
        int4 qA = *(const int4*)&sm->pi[m][hb * 8];
        int4 qB = *(const int4*)&sm->pi[m][hb * 8 + 4];
        const int pbs[8] = {qA.x, qA.y, qA.z, qA.w, qB.x, qB.y, qB.z, qB.w};
        const unsigned* tr = Fj + pa * 128 + c2;
        unsigned long long rs2 = 0ull;
#pragma unroll
        for (int k = 0; k < 8; ++k) {
            int pb = pbs[k];
            unsigned v = 0u;
            if ((pa | pb) >= 0) v = tr[pb * 8];
            unsigned long long vf = b2f2(v);
            ADD2(s0a[k], vf);
            ADD2(rs2, vf);
            if (a == m)  // d0[m][b] = T[m][b] : raw bf16x2 pass-through
                Au[(24 + c2) * BPL + swzf(m, hb * 8 + k)] = v;
        }
        {  // d1, d2 raw pass-through (dedup across hb)
            unsigned dv1 = 0u, dv2 = 0u;
            if (pa >= 0) {
                if (hb == (a >> 3)) dv2 = tr[pa * 8];
                if (hb == (m >> 3) && pm >= 0) dv1 = tr[pm * 8];
            }
            if (hb == (a >> 3)) Au[(40 + c2) * BPL + swzf(m, a)] = dv2;
            if (hb == (m >> 3)) Au[(32 + c2) * BPL + swzf(m, a)] = dv1;
        }
        float rl = lo2(rs2), rh = hi2(rs2);
        rl += __shfl_xor_sync(0xffffffffu, rl, 1);
        rh += __shfl_xor_sync(0xffffffffu, rh, 1);
        if (hb == 0) Au[(16 + c2) * BPL + swzf(m, a)] = cvtb2(rl, rh);  // s2
        v1l += rl; v1r += rh;
        // column sums (thread plays b = a)
        unsigned long long cs2 = 0ull;
        const unsigned* tc = Fj + pa * 8 + c2;
#pragma unroll
        for (int k = 0; k < 8; ++k) {
            int p2 = pbs[k];
            unsigned v = 0u;
            if ((pa | p2) >= 0) v = tc[p2 * 128];
            ADD2(cs2, b2f2(v));
        }
        float cl = lo2(cs2), ch = hi2(cs2);
        cl += __shfl_xor_sync(0xffffffffu, cl, 1);
        ch += __shfl_xor_sync(0xffffffffu, ch, 1);
        if (hb == 0) Au[(8 + c2) * BPL + swzf(m, a)] = cvtb2(cl, ch);  // s1
        v2l += cl; v2r += ch;
    }

    // stage s0 (f32) + v partials
    {
        float* stg = sm->P + g * 4224;
#pragma unroll
        for (int k = 0; k < 8; ++k)
            *(float2*)(stg + a * 264 + (hb * 8 + k) * 16 + 2 * c2) =
                make_float2(lo2(s0a[k]), hi2(s0a[k]));
        if (hb == 0) {
            *(float2*)(&sm->v1p[g][a * 16 + 2 * c2]) = make_float2(v1l, v1r);
            *(float2*)(&sm->v2p[g][a * 16 + 2 * c2]) = make_float2(v2l, v2r);
        }
    }
    __syncthreads();
    if (tid < 128) {  // v0[m][c] = sum_a s2[m][a][c] (from bf16 s2)
        int m = tid >> 3, cq = tid & 7;
        const unsigned* s2p = Au + (16 + cq) * BPL;
        float sl = 0.f, sh = 0.f;
#pragma unroll
        for (int a2 = 0; a2 < 16; ++a2) {
            unsigned v = s2p[swzf(m, a2)];
            sl += __uint_as_float(v << 16);
            sh += __uint_as_float(v & 0xffff0000u);
        }
        *(float2*)(&sm->v0[m * 16 + 2 * cq]) = make_float2(sl, sh);
    }
#pragma unroll
    for (int p = 0; p < 2; ++p) {  // combine s0 -> Asp[0] (bf16x2)
        int idx = tid + p * 1024;
        int a2 = idx >> 7, b2 = (idx >> 3) & 15, cq = idx & 7;
        int off = a2 * 264 + b2 * 16 + 2 * cq;
        float2 u0 = *(float2*)(sm->P + off);
        float2 u1 = *(float2*)(sm->P + 4224 + off);
        float2 u2 = *(float2*)(sm->P + 8448 + off);
        float2 u3 = *(float2*)(sm->P + 12672 + off);
        Au[cq * BPL + swzf(a2, b2)] =
            cvtb2(u0.x + u1.x + u2.x + u3.x, u0.y + u1.y + u2.y + u3.y);
    }
    if (tid < 256) {
        sm->v1s[tid] = sm->v1p[0][tid] + sm->v1p[1][tid] + sm->v1p[2][tid] +
                       sm->v1p[3][tid];
        sm->v2s[tid] = sm->v2p[0][tid] + sm->v2p[1][tid] + sm->v2p[2][tid] +
                       sm->v2p[3][tid];
    }
    __syncthreads();

    // ---------------- Phase B ------------------------------------------------
    if (tid < 512) {  // rowt / colt from v-blocks
        int half = tid >> 8, al = (tid >> 4) & 15, h = tid & 15;
        float acc = 0.f;
#pragma unroll
        for (int cc = 0; cc < 16; ++cc) {
            float a0 = sm->v0[al * 16 + cc];
            float a1 = sm->v1s[al * 16 + cc];
            float a2v = sm->v2s[al * 16 + cc];
            const float* wv = &sm->Wvt[(half * 16 + cc) * 16 + h];
            acc += a0 * wv[0] + a1 * wv[512] + a2v * wv[1024];
        }
        (half ? sm->colt : sm->rowt)[al * 16 + h] = acc;
    }

    const int sec = tid >> 7, u = tid & 127;
    const int ks = sec >> 1, hs = sec & 1;
    int x1, y1, x2, y2;
    bool diag;
    unrank(u, x1, y1, x2, y2, diag);
    const int sw1 = swzf(x1, y1), sw2 = swzf(x2, y2);
    const int pos1 = x1 * 16 + y1, pos2 = x2 * 16 + y2;

    unsigned long long acc1[8], acc2[8];
#pragma unroll
    for (int h = 0; h < 8; ++h) { acc1[h] = 0ull; acc2[h] = 0ull; }
    unsigned wadr = sptr(sm->Wp) + ((ks * 12) * 16 + hs * 8) * 16;

#pragma unroll 4
    for (int uu = 0; uu < 12; ++uu) {
        int kp = ks * 12 + uu;
        const unsigned* pl = sm->Asp + kp * BPL;
        unsigned long long va = b2f2(pl[sw1]);
        unsigned long long vb = b2f2(pl[sw2]);
        unsigned long long t1 = diag ? va : vb;
        unsigned long long t2 = diag ? vb : va;
#pragma unroll
        for (int hh = 0; hh < 8; ++hh) {
            unsigned long long we, wo;
            LDW2(we, wo, wadr + uu * 256 + hh * 16);
            FMA2(acc1[hh], va, we);
            FMA2(acc1[hh], t1, wo);
            FMA2(acc2[hh], vb, we);
            FMA2(acc2[hh], t2, wo);
        }
    }
    {
        float* p1 = sm->P + (sec * 256 + pos1) * 8;
        float* p2 = sm->P + (sec * 256 + pos2) * 8;
        *(float4*)p1 = make_float4(sum2(acc1[0]), sum2(acc1[1]), sum2(acc1[2]),
                                   sum2(acc1[3]));
        *(float4*)(p1 + 4) = make_float4(sum2(acc1[4]), sum2(acc1[5]),
                                         sum2(acc1[6]), sum2(acc1[7]));
        *(float4*)p2 = make_float4(sum2(acc2[0]), sum2(acc2[1]), sum2(acc2[2]),
                                   sum2(acc2[3]));
        *(float4*)(p2 + 4) = make_float4(sum2(acc2[4]), sum2(acc2[5]),
                                         sum2(acc2[6]), sum2(acc2[7]));
    }
    __syncthreads();

    // final combine + g reduction (no F output in layer 2)
    const int pos = tid >> 2, hq = tid & 3;
    const int alf = pos >> 4, bef = pos & 15;
    const int hsf = hq >> 1, hof = (hq & 1) * 4;
    float4 q0 = *(const float4*)(sm->P + ((0 + hsf) * 256 + pos) * 8 + hof);
    float4 q1 = *(const float4*)(sm->P + ((2 + hsf) * 256 + pos) * 8 + hof);
    float4 q2 = *(const float4*)(sm->P + ((4 + hsf) * 256 + pos) * 8 + hof);
    float4 q3 = *(const float4*)(sm->P + ((6 + hsf) * 256 + pos) * 8 + hof);
    float4 rw = *(const float4*)(&sm->rowt[alf * 16 + hq * 4]);
    float4 cl4 = *(const float4*)(&sm->colt[bef * 16 + hq * 4]);
    float4 bv = *(const float4*)(&sm->bb[hq * 4]);
    float vals[4];
    vals[0] = fmaxf(q0.x + q1.x + q2.x + q3.x + rw.x + cl4.x + bv.x, 0.f);
    vals[1] = fmaxf(q0.y + q1.y + q2.y + q3.y + rw.y + cl4.y + bv.y, 0.f);
    vals[2] = fmaxf(q0.z + q1.z + q2.z + q3.z + rw.z + cl4.z + bv.z, 0.f);
    vals[3] = fmaxf(q0.w + q1.w + q2.w + q3.w + rw.w + cl4.w + bv.w, 0.f);

    const int w = tid >> 5, lane = tid & 31;
#pragma unroll
    for (int k2 = 0; k2 < 4; ++k2) {
        float v = vals[k2];
        v += __shfl_xor_sync(0xffffffffu, v, 4);
        v += __shfl_xor_sync(0xffffffffu, v, 8);
        v += __shfl_xor_sync(0xffffffffu, v, 16);
        vals[k2] = v;
    }
    if (lane < 4) {
#pragma unroll
        for (int k2 = 0; k2 < 4; ++k2) sm->red[w * 16 + lane * 4 + k2] = vals[k2];
    }
    __syncthreads();
    if (tid < 16) {
        float s = 0.f;
#pragma unroll
        for (int w2 = 0; w2 < 32; ++w2) s += sm->red[w2 * 16 + tid];
        atomicAdd(&g_gsum[32 + tid], (double)s);
    }
}

// ---------------- kernel 5: final dot with fc --------------------------------
__global__ void final_kernel(const float* __restrict__ fc_w,
                             const float* __restrict__ fc_b,
                             float* __restrict__ out) {
    if (threadIdx.x == 0) {
        double s = (double)fc_b[0];
#pragma unroll
        for (int c = 0; c < 48; ++c) s += g_gsum[c] * (double)fc_w[c];
        out[0] = (float)s;
    }
}

// ---------------- host entry --------------------------------------------------
extern "C" void kernel_launch(void* const* d_in, const int* in_sizes, int n_in,
                              void* d_out, int out_size) {
    const float* X   = (const float*)d_in[0];
    const float* adj = (const float*)d_in[1];
    const float* W1  = (const float*)d_in[2];
    const float* b1  = (const float*)d_in[3];
    const float* W2  = (const float*)d_in[4];
    const float* b2  = (const float*)d_in[5];
    const float* fcw = (const float*)d_in[6];
    const float* fcb = (const float*)d_in[7];
    float* out = (float*)d_out;

    const int SMEM2 = (int)sizeof(Sm2);
    cudaFuncSetAttribute(step2_kernel,
                         cudaFuncAttributeMaxDynamicSharedMemorySize, SMEM2);

    nbrs_kernel<<<250, 256>>>(adj);
    f0sum_kernel<<<125, 256>>>(X);
    step1_kernel<<<NN, 256>>>(X, W1, b1);
    step2_kernel<<<NN, 1024, SMEM2>>>(W2, b2);
    final_kernel<<<1, 32>>>(fcw, fcb, out);
}

// round 17
// speedup vs baseline: 1.4645x; 1.4645x over previous
#include <cuda_runtime.h>

#define NN 2000
#define PS 516               // step1 f32 plane stride (floats)
#define ARRF 4128
#define AW 100               // MMA A / W row stride in u32 words (400 B)

__device__ int g_nbrs[NN * 16];
__device__ __align__(16) unsigned short g_F1b[(size_t)NN * 4096];  // bf16 F1
__device__ double g_gsum[48];

// ---------------- step2 smem layout (byte offsets) ---------------------------
#define OFF_A    0        // 102400 B : MMA A (256 x 192 bf16, row stride 400B)
#define OFF_WB   102400   // 6400 B   : W bf16x2 [h][kw], stride 400B
#define OFF_P    108800   // 67584 B  : s0 staging (4 x 4224 f32)
#define OFF_WVT  176384   // 6144
#define OFF_V0   182528   // 1024
#define OFF_V1S  183552   // 1024
#define OFF_V2S  184576   // 1024
#define OFF_V1P  185600   // 4096
#define OFF_V2P  189696   // 4096
#define OFF_ROWT 193792   // 1024
#define OFF_COLT 194816   // 1024
#define OFF_RED  195840   // 1024 (32 warps x 8 h)
#define OFF_BB   196864   // 64
#define OFF_NBI  196928   // 64
#define OFF_NBJ  196992   // 1024
#define OFF_PI   198016   // 1024
#define SMEM2_BYTES 199040

__device__ __forceinline__ unsigned sptr(const void* p) {
    return (unsigned)__cvta_generic_to_shared(p);
}
__device__ __forceinline__ float sum2(unsigned long long u) {
    return __uint_as_float((unsigned)u) + __uint_as_float((unsigned)(u >> 32));
}
__device__ __forceinline__ float lo2(unsigned long long u) {
    return __uint_as_float((unsigned)u);
}
__device__ __forceinline__ float hi2(unsigned long long u) {
    return __uint_as_float((unsigned)(u >> 32));
}
__device__ __forceinline__ unsigned cvtb2(float lo, float hi) {
    unsigned r;
    asm("cvt.rn.bf16x2.f32 %0, %1, %2;" : "=r"(r) : "f"(hi), "f"(lo));
    return r;
}
__device__ __forceinline__ unsigned long long b2f2(unsigned v) {
    unsigned lo = v << 16;
    unsigned hi = v & 0xffff0000u;
    return (unsigned long long)lo | ((unsigned long long)hi << 32);
}
#define FMA2(acc, x, y) \
    asm("fma.rn.f32x2 %0, %1, %2, %3;" : "=l"(acc) : "l"(x), "l"(y), "l"(acc))
#define ADD2(acc, x) \
    asm("add.rn.f32x2 %0, %0, %1;" : "+l"(acc) : "l"(x))
#define LDW2(we, wo, a) \
    asm("ld.shared.v2.b64 {%0,%1}, [%2];" : "=l"(we), "=l"(wo) : "r"(a))
__device__ __forceinline__ int swzf(int x, int y) {
    return x * 16 + (((y ^ x) + 5 * x) & 15);
}
__device__ __forceinline__ void unrank(int u, int& x1, int& y1, int& x2,
                                       int& y2, bool& diag) {
    if (u < 120) {
        int a = 0, rem = u;
        while (rem >= 15 - a) { rem -= 15 - a; ++a; }
        x1 = a; y1 = a + 1 + rem; x2 = y1; y2 = x1; diag = false;
    } else {
        int d = u - 120;
        x1 = 2 * d; y1 = 2 * d; x2 = 2 * d + 1; y2 = 2 * d + 1; diag = true;
    }
}

// ---------------- step1 shared layout ----------------------------------------
struct __align__(16) Sm1 {
    float Asp[ARRF];
    float4 Wp[128];
    float Wvt[1536];
    float wd1[256], wd2[256];
    float v0[256], v1s[256];
    float rowt[256], colt[256], corr[256];
    float red[8][8];
    float bb[16];
    int nbrs_i[16];
    int nbrs_j[16][16];
    __align__(16) int pi[16][16];
};

// ---------------- kernel 1: neighbor extraction + zero g --------------------
__global__ void nbrs_kernel(const float* __restrict__ adj) {
    if (blockIdx.x == 0 && threadIdx.x < 48) g_gsum[threadIdx.x] = 0.0;
    int w = blockIdx.x * (blockDim.x >> 5) + (threadIdx.x >> 5);
    int lane = threadIdx.x & 31;
    if (w >= NN) return;
    const float* row = adj + (size_t)w * NN;
    int cnt = 0;
    for (int base = 0; base < NN; base += 32) {
        int col = base + lane;
        float v = (col < NN) ? row[col] : 0.f;
        unsigned mask = __ballot_sync(0xffffffffu, v > 0.5f);
        if (v > 0.5f) {
            int pos = cnt + __popc(mask & ((1u << lane) - 1u));
            if (pos < 16) g_nbrs[w * 16 + pos] = col;
        }
        cnt += __popc(mask);
    }
}

// ---------------- kernel 2: F0 channel sums ---------------------------------
__global__ void f0sum_kernel(const float* __restrict__ X) {
    int idx = blockIdx.x * 256 + threadIdx.x;
    float loc[16];
#pragma unroll
    for (int c = 0; c < 16; ++c) loc[c] = 0.f;
    if (idx < NN * 16) {
        int node = g_nbrs[idx];
#pragma unroll
        for (int c = 0; c < 16; ++c) loc[c] = X[node * 16 + c];
    }
#pragma unroll
    for (int c = 0; c < 16; ++c) {
        float v = loc[c];
#pragma unroll
        for (int o = 16; o; o >>= 1) v += __shfl_xor_sync(0xffffffffu, v, o);
        loc[c] = v;
    }
    __shared__ float sh[8][16];
    int wid = threadIdx.x >> 5, lane = threadIdx.x & 31;
    if (lane == 0) {
#pragma unroll
        for (int c = 0; c < 16; ++c) sh[wid][c] = loc[c];
    }
    __syncthreads();
    if (threadIdx.x < 16) {
        float s = 0.f;
#pragma unroll
        for (int w = 0; w < 8; ++w) s += sh[w][threadIdx.x];
        atomicAdd(&g_gsum[threadIdx.x], (double)s);
    }
}

// ---------------- kernel 3: layer-1 step (unchanged) ------------------------
__global__ __launch_bounds__(256, 4) void step1_kernel(
    const float* __restrict__ X, const float* __restrict__ Wg,
    const float* __restrict__ bg) {
    __shared__ Sm1 sm;
    const int i = blockIdx.x;
    const int tid = threadIdx.x;

    if (tid < 16) {
        sm.nbrs_i[tid] = g_nbrs[i * 16 + tid];
        sm.bb[tid] = bg[tid];
    }
    if (tid < 128) {
        int kp = tid >> 4, h = tid & 15, cc = kp * 2;
        const float* wb = Wg + h * 288;
        sm.Wp[tid] = make_float4(
            wb[32 + cc] + wb[64 + cc] + wb[160 + cc],
            wb[33 + cc] + wb[65 + cc] + wb[161 + cc],
            wb[48 + cc] + wb[80 + cc] + wb[176 + cc],
            wb[49 + cc] + wb[81 + cc] + wb[177 + cc]);
    }
    {
        int h = tid >> 4, c = tid & 15;
        const float* wb = Wg + h * 288;
        sm.wd1[tid] = wb[c] + wb[16 + c];
        sm.wd2[tid] = wb[96 + c] + wb[112 + c] + wb[128 + c] + wb[144 + c];
    }
#pragma unroll
    for (int idx = tid; idx < 1536; idx += 256) {
        int cci = idx >> 4, h = idx & 15;
        sm.Wvt[idx] = Wg[h * 288 + 192 + cci];
    }
    __syncthreads();
    {
        int m = tid >> 4, aa = tid & 15;
        sm.nbrs_j[m][aa] = g_nbrs[sm.nbrs_i[m] * 16 + aa];
    }
    __syncthreads();
    {
        int m = tid >> 4, aa = tid & 15;
        int tgt = sm.nbrs_i[aa];
        int p = -1;
#pragma unroll
        for (int q = 0; q < 16; ++q)
            if (sm.nbrs_j[m][q] == tgt) p = q;
        sm.pi[m][aa] = p;
    }
    __syncthreads();

    {
        const int xa = tid >> 4, c = tid & 15;
        float v1acc = 0.f;
        float* asw = sm.Asp + (c >> 1) * PS + (c & 1);
#pragma unroll
        for (int m = 0; m < 16; ++m) {
            int pa = sm.pi[m][xa];
            float xv = 0.f;
            if (pa >= 0) xv = X[sm.nbrs_j[m][pa] * 16 + c];
            v1acc += xv;
            asw[swzf(m, xa) * 2] = xv;
        }
        sm.v1s[xa * 16 + c] = v1acc;
    }
    __syncthreads();
    {
        int m = tid >> 4, cx = tid & 15;
        const float* s2b = sm.Asp + (cx >> 1) * PS + (cx & 1);
        float s = 0.f;
#pragma unroll
        for (int a2 = 0; a2 < 16; ++a2) s += s2b[swzf(m, a2) * 2];
        sm.v0[m * 16 + cx] = s;
    }
    __syncthreads();
    {
        int x = tid >> 4, h = tid & 15;
        float r = 0.f, ct = 0.f, co = 0.f;
#pragma unroll
        for (int cc = 0; cc < 16; ++cc) {
            float a0 = sm.v0[x * 16 + cc];
            float a1 = sm.v1s[x * 16 + cc];
            r += a0 * sm.Wvt[cc * 16 + h] +
                 a1 * (sm.Wvt[(32 + cc) * 16 + h] + sm.Wvt[(64 + cc) * 16 + h]);
            ct += a0 * sm.Wvt[(16 + cc) * 16 + h] +
                  a1 * (sm.Wvt[(48 + cc) * 16 + h] + sm.Wvt[(80 + cc) * 16 + h]);
            float dd = sm.Asp[(cc >> 1) * PS + swzf(x, x) * 2 + (cc & 1)];
            co += a1 * sm.wd1[h * 16 + cc] + dd * sm.wd2[h * 16 + cc];
        }
        sm.rowt[x * 16 + h] = r;
        sm.colt[x * 16 + h] = ct;
        sm.corr[x * 16 + h] = co;
    }
    __syncthreads();

    const int hs = tid >> 7, u = tid & 127;
    int x1, y1, x2, y2;
    bool diag;
    unrank(u, x1, y1, x2, y2, diag);
    const int sw1 = swzf(x1, y1), sw2 = swzf(x2, y2);
    unsigned long long acc1[8], acc2[8];
#pragma unroll
    for (int h = 0; h < 8; ++h) { acc1[h] = 0ull; acc2[h] = 0ull; }
    unsigned wadr = sptr(sm.Wp) + hs * 128;
#pragma unroll
    for (int kp = 0; kp < 8; ++kp) {
        const float* pl = sm.Asp + kp * PS;
        unsigned long long va = *(const unsigned long long*)(pl + sw1 * 2);
        unsigned long long vb = *(const unsigned long long*)(pl + sw2 * 2);
        unsigned long long t1 = diag ? va : vb;
        unsigned long long t2 = diag ? vb : va;
#pragma unroll
        for (int hh = 0; hh < 8; ++hh) {
            unsigned long long we, wo;
            LDW2(we, wo, wadr + kp * 256 + hh * 16);
            FMA2(acc1[hh], va, we);
            FMA2(acc1[hh], t1, wo);
            FMA2(acc2[hh], vb, we);
            FMA2(acc2[hh], t2, wo);
        }
    }
    float g8[8];
    {
        float v1v[8], v2v[8];
#pragma unroll
        for (int hh = 0; hh < 8; ++hh) {
            int h = hs * 8 + hh;
            float v = sum2(acc1[hh]) + sm.rowt[x1 * 16 + h] +
                      sm.colt[y1 * 16 + h] + sm.bb[h];
            if (diag) v += sm.corr[x1 * 16 + h];
            v1v[hh] = fmaxf(v, 0.f);
            float w2 = sum2(acc2[hh]) + sm.rowt[x2 * 16 + h] +
                       sm.colt[y2 * 16 + h] + sm.bb[h];
            if (diag) w2 += sm.corr[x2 * 16 + h];
            v2v[hh] = fmaxf(w2, 0.f);
            g8[hh] = v1v[hh] + v2v[hh];
        }
        uint4 o1 = make_uint4(cvtb2(v1v[0], v1v[1]), cvtb2(v1v[2], v1v[3]),
                              cvtb2(v1v[4], v1v[5]), cvtb2(v1v[6], v1v[7]));
        *(uint4*)(g_F1b + (size_t)i * 4096 + (x1 * 16 + y1) * 16 + hs * 8) = o1;
        uint4 o2 = make_uint4(cvtb2(v2v[0], v2v[1]), cvtb2(v2v[2], v2v[3]),
                              cvtb2(v2v[4], v2v[5]), cvtb2(v2v[6], v2v[7]));
        *(uint4*)(g_F1b + (size_t)i * 4096 + (x2 * 16 + y2) * 16 + hs * 8) = o2;
    }
#pragma unroll
    for (int hh = 0; hh < 8; ++hh) {
#pragma unroll
        for (int o = 16; o; o >>= 1)
            g8[hh] += __shfl_xor_sync(0xffffffffu, g8[hh], o);
    }
    const int wid = tid >> 5, lane = tid & 31;
    if (lane == 0) {
#pragma unroll
        for (int hh = 0; hh < 8; ++hh) sm.red[wid][hh] = g8[hh];
    }
    __syncthreads();
    if (tid < 16) {
        int hs2 = tid >> 3, hh = tid & 7;
        float s = sm.red[hs2 * 4 + 0][hh] + sm.red[hs2 * 4 + 1][hh] +
                  sm.red[hs2 * 4 + 2][hh] + sm.red[hs2 * 4 + 3][hh];
        atomicAdd(&g_gsum[16 + hs2 * 8 + hh], (double)s);
    }
}

// ---------------- kernel 4: layer-2 step, phase B on mma.sync ---------------
__global__ __launch_bounds__(1024, 1) void step2_kernel(
    const float* __restrict__ Wg, const float* __restrict__ bg) {
    extern __shared__ char smem2[];
    char* B = smem2;
    const unsigned sb = sptr(B);

    const int i = blockIdx.x;
    const int tid = threadIdx.x;
    const int wid = tid >> 5, lane = tid & 31;
    const int g = tid >> 8, t = tid & 255;
    const int a = t >> 4, c2 = (t & 15) >> 1, hb = t & 1;

    unsigned* Au = (unsigned*)(B + OFF_A);
    unsigned* WbU = (unsigned*)(B + OFF_WB);
    float* Pf = (float*)(B + OFF_P);
    float* Wvt = (float*)(B + OFF_WVT);
    float* v0f = (float*)(B + OFF_V0);
    float* v1sf = (float*)(B + OFF_V1S);
    float* v2sf = (float*)(B + OFF_V2S);
    float* v1pf = (float*)(B + OFF_V1P);
    float* v2pf = (float*)(B + OFF_V2P);
    float* rowt = (float*)(B + OFF_ROWT);
    float* colt = (float*)(B + OFF_COLT);
    float* red = (float*)(B + OFF_RED);
    float* bbf = (float*)(B + OFF_BB);
    int* nbi = (int*)(B + OFF_NBI);
    int* nbj = (int*)(B + OFF_NBJ);
    int* piP = (int*)(B + OFF_PI);

    if (tid < 16) nbi[tid] = g_nbrs[i * 16 + tid];
    if (tid < 768) {  // pack W (dense 192 cols) as bf16x2, row stride AW words
        int kq = tid >> 4, h = tid & 15;
        float4 w4 = *(const float4*)(Wg + h * 288 + 4 * kq);
        WbU[h * AW + 2 * kq] = cvtb2(w4.x, w4.y);
        WbU[h * AW + 2 * kq + 1] = cvtb2(w4.z, w4.w);
    }
    for (int idx = tid; idx < 1536; idx += 1024) {
        int cci = idx >> 4, h = idx & 15;
        Wvt[idx] = Wg[h * 288 + 192 + cci];
    }
    if (tid >= 768 && tid < 784) bbf[tid - 768] = bg[tid - 768];
    __syncthreads();
    if (tid < 256) nbj[tid] = g_nbrs[nbi[tid >> 4] * 16 + (tid & 15)];
    __syncthreads();
    if (tid < 256) {
        int m = tid >> 4, aa = tid & 15;
        int tgt = nbi[aa];
        int p = -1;
#pragma unroll
        for (int q = 0; q < 16; ++q)
            if (nbj[m * 16 + q] == tgt) p = q;
        piP[m * 16 + aa] = p;
    }
    __syncthreads();

    // ---- Phase A: bf16 gathers -> MMA A matrix (row-major, stride AW) ------
    unsigned long long s0a[8];
#pragma unroll
    for (int k = 0; k < 8; ++k) s0a[k] = 0ull;
    float v1l = 0.f, v1r = 0.f, v2l = 0.f, v2r = 0.f;

#pragma unroll
    for (int iter = 0; iter < 4; ++iter) {
        const int m = iter * 4 + g;
        const int j = nbi[m];
        const unsigned* Fj = (const unsigned*)g_F1b + (size_t)j * 2048;
        const int pa = piP[m * 16 + a];
        const int pm = piP[m * 16 + m];
        int4 qA = *(const int4*)&piP[m * 16 + hb * 8];
        int4 qB = *(const int4*)&piP[m * 16 + hb * 8 + 4];
        const int pbs[8] = {qA.x, qA.y, qA.z, qA.w, qB.x, qB.y, qB.z, qB.w};
        const unsigned* tr = Fj + pa * 128 + c2;
        unsigned long long rs2 = 0ull;
#pragma unroll
        for (int k = 0; k < 8; ++k) {
            int pb = pbs[k];
            unsigned v = 0u;
            if ((pa | pb) >= 0) v = tr[pb * 8];
            unsigned long long vf = b2f2(v);
            ADD2(s0a[k], vf);
            ADD2(rs2, vf);
            if (a == m) {  // d0: slots 6 (a,b) / 7 (transposed)
                int b = hb * 8 + k;
                Au[(m * 16 + b) * AW + 48 + c2] = v;
                Au[(b * 16 + m) * AW + 56 + c2] = v;
            }
        }
        {  // d1 (slots 8/9), d2 (slots 10/11)
            unsigned dv1 = 0u, dv2 = 0u;
            if (pa >= 0) {
                if (hb == (a >> 3)) dv2 = tr[pa * 8];
                if (hb == (m >> 3) && pm >= 0) dv1 = tr[pm * 8];
            }
            if (hb == (a >> 3)) {
                Au[(m * 16 + a) * AW + 80 + c2] = dv2;
                Au[(a * 16 + m) * AW + 88 + c2] = dv2;
            }
            if (hb == (m >> 3)) {
                Au[(m * 16 + a) * AW + 64 + c2] = dv1;
                Au[(a * 16 + m) * AW + 72 + c2] = dv1;
            }
        }
        float rl = lo2(rs2), rh = hi2(rs2);
        rl += __shfl_xor_sync(0xffffffffu, rl, 1);
        rh += __shfl_xor_sync(0xffffffffu, rh, 1);
        {  // s2: slots 4/5
            unsigned sv = cvtb2(rl, rh);
            if (hb == 0)
                Au[(m * 16 + a) * AW + 32 + c2] = sv;
            else
                Au[(a * 16 + m) * AW + 40 + c2] = sv;
        }
        v1l += rl; v1r += rh;
        // column sums -> s1 (slots 2/3)
        unsigned long long cs2 = 0ull;
        const unsigned* tc = Fj + pa * 8 + c2;
#pragma unroll
        for (int k = 0; k < 8; ++k) {
            int p2 = pbs[k];
            unsigned v = 0u;
            if ((pa | p2) >= 0) v = tc[p2 * 128];
            ADD2(cs2, b2f2(v));
        }
        float cl = lo2(cs2), ch = hi2(cs2);
        cl += __shfl_xor_sync(0xffffffffu, cl, 1);
        ch += __shfl_xor_sync(0xffffffffu, ch, 1);
        {
            unsigned sv = cvtb2(cl, ch);
            if (hb == 0)
                Au[(m * 16 + a) * AW + 16 + c2] = sv;
            else
                Au[(a * 16 + m) * AW + 24 + c2] = sv;
        }
        v2l += cl; v2r += ch;
    }
    // stage s0 (f32) + v partials
    {
        float* stg = Pf + g * 4224;
#pragma unroll
        for (int k = 0; k < 8; ++k)
            *(float2*)(stg + a * 264 + (hb * 8 + k) * 16 + 2 * c2) =
                make_float2(lo2(s0a[k]), hi2(s0a[k]));
        if (hb == 0) {
            *(float2*)(v1pf + g * 256 + a * 16 + 2 * c2) = make_float2(v1l, v1r);
            *(float2*)(v2pf + g * 256 + a * 16 + 2 * c2) = make_float2(v2l, v2r);
        }
    }
    __syncthreads();

    // combine s0 -> A slots 0/1
#pragma unroll
    for (int p = 0; p < 2; ++p) {
        int idx = tid + p * 1024;
        int a2 = idx >> 7, b2 = (idx >> 3) & 15, cq = idx & 7;
        int off = a2 * 264 + b2 * 16 + 2 * cq;
        float2 u0 = *(float2*)(Pf + off);
        float2 u1 = *(float2*)(Pf + 4224 + off);
        float2 u2 = *(float2*)(Pf + 8448 + off);
        float2 u3 = *(float2*)(Pf + 12672 + off);
        unsigned v = cvtb2(u0.x + u1.x + u2.x + u3.x, u0.y + u1.y + u2.y + u3.y);
        Au[(a2 * 16 + b2) * AW + cq] = v;
        Au[(b2 * 16 + a2) * AW + 8 + cq] = v;
    }
    if (tid < 128) {  // v0[m][c] from s2 slot (staggered a)
        int m = tid >> 3, cq = tid & 7;
        float sl = 0.f, sh = 0.f;
#pragma unroll
        for (int aa = 0; aa < 16; ++aa) {
            int a2 = (aa + m) & 15;
            unsigned v = Au[(m * 16 + a2) * AW + 32 + cq];
            sl += __uint_as_float(v << 16);
            sh += __uint_as_float(v & 0xffff0000u);
        }
        *(float2*)(v0f + m * 16 + 2 * cq) = make_float2(sl, sh);
    }
    if (tid >= 256 && tid < 512) {
        int tt = tid - 256;
        v1sf[tt] = v1pf[tt] + v1pf[256 + tt] + v1pf[512 + tt] + v1pf[768 + tt];
        v2sf[tt] = v2pf[tt] + v2pf[256 + tt] + v2pf[512 + tt] + v2pf[768 + tt];
    }
    __syncthreads();

    // ---- Phase B: rowt/colt (warps 0-15) + warp-MMA GEMM (all warps) -------
    if (tid < 512) {
        int half = tid >> 8, al = (tid >> 4) & 15, h = tid & 15;
        float acc = 0.f;
#pragma unroll
        for (int cc = 0; cc < 16; ++cc) {
            float a0 = v0f[al * 16 + cc];
            float a1 = v1sf[al * 16 + cc];
            float a2v = v2sf[al * 16 + cc];
            const float* wv = &Wvt[(half * 16 + cc) * 16 + h];
            acc += a0 * wv[0] + a1 * wv[512] + a2v * wv[1024];
        }
        (half ? colt : rowt)[al * 16 + h] = acc;
    }

    // warp wid -> row tile (wid&15), h-half (wid>>4)
    const int rtile = wid & 15, nhalf = wid >> 4;
    const int gid = lane >> 2, tig = lane & 3;
    float c0 = 0.f, c1 = 0.f, c2f = 0.f, c3 = 0.f;
    {
        const int arow = rtile * 16 + (lane & 7) + (lane & 8);
        const int acolw = (lane & 16) ? 4 : 0;
        unsigned aAddr = sb + OFF_A + (unsigned)(arow * AW + acolw) * 4u;
        const unsigned* wrow = WbU + (nhalf * 8 + gid) * AW + tig;
#pragma unroll
        for (int u = 0; u < 12; ++u) {
            unsigned a0, a1, a2, a3;
            asm volatile(
                "ldmatrix.sync.aligned.m8n8.x4.shared.b16 {%0,%1,%2,%3}, [%4];"
                : "=r"(a0), "=r"(a1), "=r"(a2), "=r"(a3)
                : "r"(aAddr + (unsigned)u * 32u));
            unsigned b0 = wrow[8 * u];
            unsigned b1 = wrow[8 * u + 4];
            asm volatile(
                "mma.sync.aligned.m16n8k16.row.col.f32.bf16.bf16.f32 "
                "{%0,%1,%2,%3}, {%4,%5,%6,%7}, {%8,%9}, {%0,%1,%2,%3};"
                : "+f"(c0), "+f"(c1), "+f"(c2f), "+f"(c3)
                : "r"(a0), "r"(a1), "r"(a2), "r"(a3), "r"(b0), "r"(b1));
        }
    }
    __syncthreads();

    // ---- Epilogue: finalize in-register, reduce into g ---------------------
    {
        int h0 = nhalf * 8 + 2 * tig;
        float rw0 = rowt[rtile * 16 + h0], rw1 = rowt[rtile * 16 + h0 + 1];
        float cl0a = colt[gid * 16 + h0], cl1a = colt[gid * 16 + h0 + 1];
        float cl0b = colt[(gid + 8) * 16 + h0], cl1b = colt[(gid + 8) * 16 + h0 + 1];
        float b0f = bbf[h0], b1f = bbf[h0 + 1];
        float v00 = fmaxf(c0 + rw0 + cl0a + b0f, 0.f);
        float v01 = fmaxf(c1 + rw1 + cl1a + b1f, 0.f);
        float v10 = fmaxf(c2f + rw0 + cl0b + b0f, 0.f);
        float v11 = fmaxf(c3 + rw1 + cl1b + b1f, 0.f);
        float p0 = v00 + v10, p1 = v01 + v11;
        p0 += __shfl_xor_sync(0xffffffffu, p0, 4);
        p0 += __shfl_xor_sync(0xffffffffu, p0, 8);
        p0 += __shfl_xor_sync(0xffffffffu, p0, 16);
        p1 += __shfl_xor_sync(0xffffffffu, p1, 4);
        p1 += __shfl_xor_sync(0xffffffffu, p1, 8);
        p1 += __shfl_xor_sync(0xffffffffu, p1, 16);
        if (lane < 4) {
            red[wid * 8 + 2 * lane] = p0;
            red[wid * 8 + 2 * lane + 1] = p1;
        }
    }
    __syncthreads();
    if (tid < 16) {
        int half = tid >> 3;
        float s = 0.f;
#pragma unroll
        for (int w2 = 0; w2 < 16; ++w2)
            s += red[(half * 16 + w2) * 8 + (tid & 7)];
        atomicAdd(&g_gsum[32 + tid], (double)s);
    }
}

// ---------------- kernel 5: final dot with fc --------------------------------
__global__ void final_kernel(const float* __restrict__ fc_w,
                             const float* __restrict__ fc_b,
                             float* __restrict__ out) {
    if (threadIdx.x == 0) {
        double s = (double)fc_b[0];
#pragma unroll
        for (int c = 0; c < 48; ++c) s += g_gsum[c] * (double)fc_w[c];
        out[0] = (float)s;
    }
}

// ---------------- host entry --------------------------------------------------
extern "C" void kernel_launch(void* const* d_in, const int* in_sizes, int n_in,
                              void* d_out, int out_size) {
    const float* X   = (const float*)d_in[0];
    const float* adj = (const float*)d_in[1];
    const float* W1  = (const float*)d_in[2];
    const float* b1  = (const float*)d_in[3];
    const float* W2  = (const float*)d_in[4];
    const float* b2  = (const float*)d_in[5];
    const float* fcw = (const float*)d_in[6];
    const float* fcb = (const float*)d_in[7];
    float* out = (float*)d_out;

    cudaFuncSetAttribute(step2_kernel,
                         cudaFuncAttributeMaxDynamicSharedMemorySize,
                         SMEM2_BYTES);

    nbrs_kernel<<<250, 256>>>(adj);
    f0sum_kernel<<<125, 256>>>(X);
    step1_kernel<<<NN, 256>>>(X, W1, b1);
    step2_kernel<<<NN, 1024, SMEM2_BYTES>>>(W2, b2);
    final_kernel<<<1, 32>>>(fcw, fcb, out);
}